// round 3
// baseline (speedup 1.0000x reference)
#include <cuda_runtime.h>
#include <math_constants.h>

#define N_OSC   60
#define BDIM    128
#define TI      12          // i-tile size (accumulator block)
#define NTILES  5           // 60 / 12
#define STEPS   10

// shared layout (floats): S[128*60] | C[128*60] | Om[64]
#define SMEM_FLOATS (BDIM*60 + BDIM*60 + 64)
#define SMEM_BYTES  (SMEM_FLOATS * 4)

__global__ __launch_bounds__(BDIM, 3)
void kuramoto_kernel(const float* __restrict__ theta,
                     const float* __restrict__ K,
                     const float* __restrict__ omega,
                     const float* __restrict__ p_Kg,
                     const float* __restrict__ p_cm,
                     const float* __restrict__ p_gate,
                     const float* __restrict__ p_csf,
                     const float* __restrict__ p_ds,
                     const float* __restrict__ p_rt,
                     float* __restrict__ out,
                     int B)
{
    extern __shared__ float smem[];
    float* sS  = smem;                 // [tid][60] per-thread sin snapshot
    float* sC  = sS + BDIM * 60;       // [tid][60] per-thread cos snapshot
    float* sOm = sC + BDIM * 60;       // raw omega [60]

    const int tid = threadIdx.x;
    const int b   = blockIdx.x * BDIM + tid;

    // ---- scalar factors, emulating the reference's fp32 op order exactly ----
    const float cf     = __fdiv_rn(1.0f, __fadd_rn(1.0f, __fmul_rn(p_csf[0], p_rt[0])));
    const float eff_dt = __fmul_rn(0.1f, cf);
    const float boost  = __fadd_rn(1.0f, __fmul_rn(p_gate[0], p_ds[0]));
    const float scale  = __fdiv_rn(__fmul_rn(p_Kg[0], boost), (float)N_OSC);
    // coupling_mod folded into scale (K read raw from gmem); ~1ulp-level noise
    // on the coupling path, which is tolerant (R2 empirically at 1.8e-7).
    const float scale2 = __fmul_rn(scale, p_cm[0]);

    if (tid < N_OSC) sOm[tid] = omega[tid];

    // ---- theta state lives in registers (all indices static after unroll) ----
    float th[N_OSC];
    {
        const float4* th4 = (const float4*)(theta + (size_t)b * N_OSC);
        #pragma unroll
        for (int j4 = 0; j4 < 15; ++j4) {
            float4 v = th4[j4];
            th[4*j4 + 0] = v.x;
            th[4*j4 + 1] = v.y;
            th[4*j4 + 2] = v.z;
            th[4*j4 + 3] = v.w;
        }
    }
    __syncthreads();   // omega cooperative load

    float* sSr = sS + tid * 60;
    float* sCr = sC + tid * 60;

    for (int step = 0; step < STEPS; ++step) {
        // ---- snapshot sin/cos of current theta (feeds coupling only) ----
        #pragma unroll
        for (int j4 = 0; j4 < 15; ++j4) {
            float4 sv, cv;
            __sincosf(th[4*j4 + 0], &sv.x, &cv.x);
            __sincosf(th[4*j4 + 1], &sv.y, &cv.y);
            __sincosf(th[4*j4 + 2], &sv.z, &cv.z);
            __sincosf(th[4*j4 + 3], &sv.w, &cv.w);
            *(float4*)&sSr[4*j4] = sv;
            *(float4*)&sCr[4*j4] = cv;
        }
        // no sync: each thread reads only its own rows

        // ---- matvec (K @ s, K @ c) in i-tiles of TI, then ref-exact update ----
        #pragma unroll
        for (int it = 0; it < NTILES; ++it) {
            const int i0 = it * TI;
            float accS[TI], accC[TI];
            #pragma unroll
            for (int u = 0; u < TI; ++u) { accS[u] = 0.f; accC[u] = 0.f; }

            #pragma unroll 3
            for (int j4 = 0; j4 < 15; ++j4) {
                float4 s4 = *(const float4*)&sSr[4*j4];
                float4 c4 = *(const float4*)&sCr[4*j4];
                #pragma unroll
                for (int u = 0; u < TI; ++u) {
                    // uniform-address LDG.128, L1-resident (14.4 KB total)
                    float4 k4 = __ldg((const float4*)&K[(i0 + u)*60 + 4*j4]);
                    accS[u] = fmaf(k4.x, s4.x, fmaf(k4.y, s4.y,
                              fmaf(k4.z, s4.z, fmaf(k4.w, s4.w, accS[u]))));
                    accC[u] = fmaf(k4.x, c4.x, fmaf(k4.y, c4.y,
                              fmaf(k4.z, c4.z, fmaf(k4.w, c4.w, accC[u]))));
                }
            }

            #pragma unroll
            for (int u = 0; u < TI; ++u) {
                const int i = i0 + u;
                const float si = sSr[i];
                const float ci = sCr[i];
                // coupling = cm * (cos_i * sum(K*sin) - sin_i * sum(K*cos)),
                // with cm folded into scale2
                const float coupling = __fadd_rn(__fmul_rn(ci, accS[u]),
                                                 -__fmul_rn(si, accC[u]));
                // reference op order: t = th + eff_dt*(omega + scale*coupling)
                const float tmp = __fadd_rn(sOm[i], __fmul_rn(scale2, coupling));
                const float t   = __fadd_rn(th[i], __fmul_rn(eff_dt, tmp));
                // reference wrap: atan2(sin t, cos t) — precise libdevice fns
                th[i] = atan2f(sinf(t), cosf(t));
            }
        }
    }

    // ---- output: theta [b*60 + j], then coherence at [B*60 + b] ----
    float ssum = 0.f, csum = 0.f;
    float4* o4 = (float4*)(out + (size_t)b * N_OSC);
    #pragma unroll
    for (int j4 = 0; j4 < 15; ++j4) {
        float4 v;
        v.x = th[4*j4 + 0];
        v.y = th[4*j4 + 1];
        v.z = th[4*j4 + 2];
        v.w = th[4*j4 + 3];
        o4[j4] = v;
        ssum += sinf(v.x); csum += cosf(v.x);
        ssum += sinf(v.y); csum += cosf(v.y);
        ssum += sinf(v.z); csum += cosf(v.z);
        ssum += sinf(v.w); csum += cosf(v.w);
    }
    ssum = __fmul_rn(ssum, 1.0f / (float)N_OSC);
    csum = __fmul_rn(csum, 1.0f / (float)N_OSC);
    out[(size_t)B * N_OSC + b] = sqrtf(__fadd_rn(__fmul_rn(csum, csum),
                                                 __fmul_rn(ssum, ssum)));
}

extern "C" void kernel_launch(void* const* d_in, const int* in_sizes, int n_in,
                              void* d_out, int out_size)
{
    const float* theta = (const float*)d_in[0];
    const float* K     = (const float*)d_in[1];
    const float* omega = (const float*)d_in[2];
    const float* p_Kg   = (const float*)d_in[3];
    const float* p_cm   = (const float*)d_in[4];
    const float* p_gate = (const float*)d_in[5];
    const float* p_csf  = (const float*)d_in[6];
    const float* p_ds   = (const float*)d_in[7];
    const float* p_rt   = (const float*)d_in[8];
    float* out = (float*)d_out;

    const int B = in_sizes[0] / N_OSC;
    const int grid = B / BDIM;

    cudaFuncSetAttribute(kuramoto_kernel,
                         cudaFuncAttributeMaxDynamicSharedMemorySize, SMEM_BYTES);

    kuramoto_kernel<<<grid, BDIM, SMEM_BYTES>>>(
        theta, K, omega, p_Kg, p_cm, p_gate, p_csf, p_ds, p_rt, out, B);
}

// round 4
// speedup vs baseline: 1.1357x; 1.1357x over previous
#include <cuda_runtime.h>
#include <math_constants.h>

#define N_OSC   60
#define BDIM    64
#define TI      20          // i-tile size (accumulator block)
#define NTILES  3           // 60 / 20
#define STEPS   10

// shared layout (floats): Keff[3600] | S[64*60] | C[64*60] | Om[64]
#define SMEM_FLOATS (3600 + BDIM*60 + BDIM*60 + 64)
#define SMEM_BYTES  (SMEM_FLOATS * 4)

__global__ __launch_bounds__(BDIM, 5)
void kuramoto_kernel(const float* __restrict__ theta,
                     const float* __restrict__ K,
                     const float* __restrict__ omega,
                     const float* __restrict__ p_Kg,
                     const float* __restrict__ p_cm,
                     const float* __restrict__ p_gate,
                     const float* __restrict__ p_csf,
                     const float* __restrict__ p_ds,
                     const float* __restrict__ p_rt,
                     float* __restrict__ out,
                     int B)
{
    extern __shared__ float smem[];
    float* sK  = smem;                 // K_eff = K * coupling_mod (ref-exact), broadcast reads
    float* sS  = sK + 3600;            // [tid][60] per-thread sin snapshot
    float* sC  = sS + BDIM * 60;       // [tid][60] per-thread cos snapshot
    float* sOm = sC + BDIM * 60;       // raw omega [60]

    const int tid = threadIdx.x;
    const int b   = blockIdx.x * BDIM + tid;

    // ---- scalar factors, emulating the reference's fp32 op order exactly (R2) ----
    const float cf     = __fdiv_rn(1.0f, __fadd_rn(1.0f, __fmul_rn(p_csf[0], p_rt[0])));
    const float eff_dt = __fmul_rn(0.1f, cf);
    const float boost  = __fadd_rn(1.0f, __fmul_rn(p_gate[0], p_ds[0]));
    const float scale  = __fdiv_rn(__fmul_rn(p_Kg[0], boost), (float)N_OSC);

    // K_eff = K * coupling_mod, elementwise — bitwise identical to reference (R2)
    {
        const float cm = p_cm[0];
        for (int idx = tid; idx < 3600; idx += BDIM) sK[idx] = __fmul_rn(K[idx], cm);
    }
    if (tid < N_OSC) sOm[tid] = omega[tid];

    // ---- theta state in registers (all indices static after unroll) ----
    float th[N_OSC];
    {
        const float4* th4 = (const float4*)(theta + (size_t)b * N_OSC);
        #pragma unroll
        for (int j4 = 0; j4 < 15; ++j4) {
            float4 v = th4[j4];
            th[4*j4 + 0] = v.x;
            th[4*j4 + 1] = v.y;
            th[4*j4 + 2] = v.z;
            th[4*j4 + 3] = v.w;
        }
    }
    __syncthreads();   // K/omega cooperative load

    float* sSr = sS + tid * 60;
    float* sCr = sC + tid * 60;

    for (int step = 0; step < STEPS; ++step) {
        // ---- snapshot sin/cos of current theta (fast path; feeds coupling only) ----
        #pragma unroll
        for (int j4 = 0; j4 < 15; ++j4) {
            float4 sv, cv;
            __sincosf(th[4*j4 + 0], &sv.x, &cv.x);
            __sincosf(th[4*j4 + 1], &sv.y, &cv.y);
            __sincosf(th[4*j4 + 2], &sv.z, &cv.z);
            __sincosf(th[4*j4 + 3], &sv.w, &cv.w);
            *(float4*)&sSr[4*j4] = sv;
            *(float4*)&sCr[4*j4] = cv;
        }
        // no sync: each thread reads only its own rows; K is read-only

        // ---- matvec (Keff @ s, Keff @ c) in i-tiles of TI, then ref-exact update ----
        #pragma unroll
        for (int it = 0; it < NTILES; ++it) {
            const int i0 = it * TI;
            float accS[TI], accC[TI];
            #pragma unroll
            for (int u = 0; u < TI; ++u) { accS[u] = 0.f; accC[u] = 0.f; }

            #pragma unroll
            for (int j4 = 0; j4 < 15; ++j4) {
                float4 s4 = *(const float4*)&sSr[4*j4];
                float4 c4 = *(const float4*)&sCr[4*j4];
                #pragma unroll
                for (int u = 0; u < TI; ++u) {
                    float4 k4 = *(const float4*)&sK[(i0 + u)*60 + 4*j4]; // warp-broadcast LDS
                    accS[u] = fmaf(k4.x, s4.x, fmaf(k4.y, s4.y,
                              fmaf(k4.z, s4.z, fmaf(k4.w, s4.w, accS[u]))));
                    accC[u] = fmaf(k4.x, c4.x, fmaf(k4.y, c4.y,
                              fmaf(k4.z, c4.z, fmaf(k4.w, c4.w, accC[u]))));
                }
            }

            // epilogue: read si/ci as float4 chunks (conflict-free), ref-exact update
            #pragma unroll
            for (int q = 0; q < TI/4; ++q) {
                const int i = i0 + 4*q;
                float4 s4 = *(const float4*)&sSr[i];
                float4 c4 = *(const float4*)&sCr[i];
                const float sv[4] = {s4.x, s4.y, s4.z, s4.w};
                const float cv[4] = {c4.x, c4.y, c4.z, c4.w};
                #pragma unroll
                for (int r = 0; r < 4; ++r) {
                    const int u  = 4*q + r;
                    const int ii = i + r;
                    // coupling = cos_i * sum(Keff*sin) - sin_i * sum(Keff*cos)
                    const float coupling = __fadd_rn(__fmul_rn(cv[r], accS[u]),
                                                     -__fmul_rn(sv[r], accC[u]));
                    // reference op order: t = th + eff_dt*(omega + scale*coupling)
                    const float tmp = __fadd_rn(sOm[ii], __fmul_rn(scale, coupling));
                    const float t   = __fadd_rn(th[ii], __fmul_rn(eff_dt, tmp));
                    // reference wrap: atan2(sin t, cos t) — precise libdevice,
                    // fused range reduction (sincosf == {sinf, cosf} bitwise)
                    float sw, cw;
                    sincosf(t, &sw, &cw);
                    th[ii] = atan2f(sw, cw);
                }
            }
        }
    }

    // ---- output: theta [b*60 + j], then coherence at [B*60 + b] ----
    float ssum = 0.f, csum = 0.f;
    float4* o4 = (float4*)(out + (size_t)b * N_OSC);
    #pragma unroll
    for (int j4 = 0; j4 < 15; ++j4) {
        float4 v;
        v.x = th[4*j4 + 0];
        v.y = th[4*j4 + 1];
        v.z = th[4*j4 + 2];
        v.w = th[4*j4 + 3];
        o4[j4] = v;
        float s, c;
        sincosf(v.x, &s, &c); ssum += s; csum += c;
        sincosf(v.y, &s, &c); ssum += s; csum += c;
        sincosf(v.z, &s, &c); ssum += s; csum += c;
        sincosf(v.w, &s, &c); ssum += s; csum += c;
    }
    ssum = __fmul_rn(ssum, 1.0f / (float)N_OSC);
    csum = __fmul_rn(csum, 1.0f / (float)N_OSC);
    out[(size_t)B * N_OSC + b] = sqrtf(__fadd_rn(__fmul_rn(csum, csum),
                                                 __fmul_rn(ssum, ssum)));
}

extern "C" void kernel_launch(void* const* d_in, const int* in_sizes, int n_in,
                              void* d_out, int out_size)
{
    const float* theta = (const float*)d_in[0];
    const float* K     = (const float*)d_in[1];
    const float* omega = (const float*)d_in[2];
    const float* p_Kg   = (const float*)d_in[3];
    const float* p_cm   = (const float*)d_in[4];
    const float* p_gate = (const float*)d_in[5];
    const float* p_csf  = (const float*)d_in[6];
    const float* p_ds   = (const float*)d_in[7];
    const float* p_rt   = (const float*)d_in[8];
    float* out = (float*)d_out;

    const int B = in_sizes[0] / N_OSC;
    const int grid = B / BDIM;

    cudaFuncSetAttribute(kuramoto_kernel,
                         cudaFuncAttributeMaxDynamicSharedMemorySize, SMEM_BYTES);

    kuramoto_kernel<<<grid, BDIM, SMEM_BYTES>>>(
        theta, K, omega, p_Kg, p_cm, p_gate, p_csf, p_ds, p_rt, out, B);
}

// round 5
// speedup vs baseline: 1.5624x; 1.3758x over previous
#include <cuda_runtime.h>
#include <math_constants.h>

#define N_OSC   60
#define BDIM    128
#define TI      12          // i-tile size (must be multiple of 4)
#define NTILES  5           // 60 / 12
#define NPAIR   (TI/2)      // packed i-pairs per tile
#define STEPS   10
#define SCSTRIDE 124        // floats per thread row in sSC (124 % 32 == 28 -> conflict-free)

// shared layout (floats): KT[60*64] | SC[128*124] | Th[60*128] | Om[64]
#define SMEM_FLOATS (60*64 + BDIM*SCSTRIDE + 60*BDIM + 64)
#define SMEM_BYTES  (SMEM_FLOATS * 4)

// packed f32x2 helpers (sm_103a; ptxas never emits FFMA2 from C++)
#define FMA_F32X2(d, a, b) \
    asm("fma.rn.f32x2 %0, %1, %2, %0;" : "+l"(d) : "l"(a), "l"(b))
#define PACK_DUP(d, x) \
    asm("mov.b64 %0, {%1, %1};" : "=l"(d) : "r"(__float_as_uint(x)))
#define UNPACK2(lo, hi, in) \
    asm("mov.b64 {%0, %1}, %2;" : "=f"(lo), "=f"(hi) : "l"(in))

__global__ __launch_bounds__(BDIM, 2)
void kuramoto_kernel(const float* __restrict__ theta,
                     const float* __restrict__ K,
                     const float* __restrict__ omega,
                     const float* __restrict__ p_Kg,
                     const float* __restrict__ p_cm,
                     const float* __restrict__ p_gate,
                     const float* __restrict__ p_csf,
                     const float* __restrict__ p_ds,
                     const float* __restrict__ p_rt,
                     float* __restrict__ out,
                     int B)
{
    extern __shared__ float smem[];
    float* sKT = smem;                     // K_eff^T: [j][i], row stride 64, broadcast reads
    float* sSC = sKT + 60*64;              // [tid][(s,c) x 60], row stride 124
    float* sTh = sSC + BDIM*SCSTRIDE;      // [i][tid], stride BDIM
    float* sOm = sTh + 60*BDIM;            // raw omega [60]

    const int tid = threadIdx.x;
    const int b   = blockIdx.x * BDIM + tid;

    // ---- scalar factors, emulating the reference's fp32 op order exactly ----
    const float cf     = __fdiv_rn(1.0f, __fadd_rn(1.0f, __fmul_rn(p_csf[0], p_rt[0])));
    const float eff_dt = __fmul_rn(0.1f, cf);
    const float boost  = __fadd_rn(1.0f, __fmul_rn(p_gate[0], p_ds[0]));
    const float scale  = __fdiv_rn(__fmul_rn(p_Kg[0], boost), (float)N_OSC);

    // K_eff = K * coupling_mod (ref-exact elementwise), stored TRANSPOSED [j][i]
    {
        const float cm = p_cm[0];
        for (int idx = tid; idx < 3600; idx += BDIM) {
            const int i = idx / 60, j = idx % 60;
            sKT[j*64 + i] = __fmul_rn(K[idx], cm);
        }
    }
    if (tid < N_OSC) sOm[tid] = omega[tid];

    // theta into transposed smem [i][tid] (coalesced-per-thread float4 in)
    {
        const float4* th4 = (const float4*)(theta + (size_t)b * N_OSC);
        #pragma unroll
        for (int j4 = 0; j4 < 15; ++j4) {
            float4 v = th4[j4];
            sTh[(4*j4 + 0)*BDIM + tid] = v.x;
            sTh[(4*j4 + 1)*BDIM + tid] = v.y;
            sTh[(4*j4 + 2)*BDIM + tid] = v.z;
            sTh[(4*j4 + 3)*BDIM + tid] = v.w;
        }
    }
    __syncthreads();   // K/omega cooperative load

    float* sSCr = sSC + tid * SCSTRIDE;

    for (int step = 0; step < STEPS; ++step) {
        // ---- snapshot sin/cos interleaved (s,c,s,c...) — coupling path only ----
        #pragma unroll
        for (int j4 = 0; j4 < 15; ++j4) {
            float4 v1, v2;
            __sincosf(sTh[(4*j4 + 0)*BDIM + tid], &v1.x, &v1.y);
            __sincosf(sTh[(4*j4 + 1)*BDIM + tid], &v1.z, &v1.w);
            __sincosf(sTh[(4*j4 + 2)*BDIM + tid], &v2.x, &v2.y);
            __sincosf(sTh[(4*j4 + 3)*BDIM + tid], &v2.z, &v2.w);
            *(float4*)&sSCr[8*j4]     = v1;
            *(float4*)&sSCr[8*j4 + 4] = v2;
        }
        // no sync: each thread touches only its own sSC row / sTh column

        // ---- packed matvec: acc2[p] covers rows (i0+2p, i0+2p+1) ----
        #pragma unroll
        for (int it = 0; it < NTILES; ++it) {
            const int i0 = it * TI;
            unsigned long long accS[NPAIR], accC[NPAIR];
            #pragma unroll
            for (int p = 0; p < NPAIR; ++p) { accS[p] = 0ull; accC[p] = 0ull; }

            for (int j4 = 0; j4 < 15; ++j4) {
                // (s,c) pairs for 4 consecutive j
                float4 p0 = *(const float4*)&sSCr[8*j4];      // s_j0,c_j0,s_j1,c_j1
                float4 p1 = *(const float4*)&sSCr[8*j4 + 4];  // s_j2,c_j2,s_j3,c_j3
                const float sj[4] = {p0.x, p0.z, p1.x, p1.z};
                const float cj[4] = {p0.y, p0.w, p1.y, p1.w};
                #pragma unroll
                for (int m = 0; m < 4; ++m) {
                    const int j = 4*j4 + m;
                    unsigned long long sd, cd;
                    PACK_DUP(sd, sj[m]);
                    PACK_DUP(cd, cj[m]);
                    // K^T row j, columns i0..i0+11: broadcast ulonglong2 loads
                    // each .x/.y is already a packed (k_i, k_i+1) f32x2 operand
                    const ulonglong2* kp = (const ulonglong2*)&sKT[j*64 + i0];
                    #pragma unroll
                    for (int q = 0; q < NPAIR/2; ++q) {       // 3 loads of 2 pairs
                        ulonglong2 kk = kp[q];
                        FMA_F32X2(accS[2*q + 0], kk.x, sd);
                        FMA_F32X2(accC[2*q + 0], kk.x, cd);
                        FMA_F32X2(accS[2*q + 1], kk.y, sd);
                        FMA_F32X2(accC[2*q + 1], kk.y, cd);
                    }
                }
            }

            // ---- epilogue: ref-exact update + libdevice wrap ----
            #pragma unroll
            for (int p = 0; p < NPAIR; ++p) {
                const int i = i0 + 2*p;
                float aS0, aS1, aC0, aC1;
                UNPACK2(aS0, aS1, accS[p]);
                UNPACK2(aC0, aC1, accC[p]);
                float2 sc0 = *(const float2*)&sSCr[2*i];       // (s_i,   c_i)
                float2 sc1 = *(const float2*)&sSCr[2*i + 2];   // (s_i+1, c_i+1)

                {   // element i
                    const float coupling = __fadd_rn(__fmul_rn(sc0.y, aS0),
                                                     -__fmul_rn(sc0.x, aC0));
                    const float tmp = __fadd_rn(sOm[i], __fmul_rn(scale, coupling));
                    const float t   = __fadd_rn(sTh[i*BDIM + tid], __fmul_rn(eff_dt, tmp));
                    float sw, cw; sincosf(t, &sw, &cw);
                    sTh[i*BDIM + tid] = atan2f(sw, cw);
                }
                {   // element i+1
                    const float coupling = __fadd_rn(__fmul_rn(sc1.y, aS1),
                                                     -__fmul_rn(sc1.x, aC1));
                    const float tmp = __fadd_rn(sOm[i+1], __fmul_rn(scale, coupling));
                    const float t   = __fadd_rn(sTh[(i+1)*BDIM + tid], __fmul_rn(eff_dt, tmp));
                    float sw, cw; sincosf(t, &sw, &cw);
                    sTh[(i+1)*BDIM + tid] = atan2f(sw, cw);
                }
            }
        }
    }

    // ---- output: theta [b*60 + j], then coherence at [B*60 + b] ----
    float ssum = 0.f, csum = 0.f;
    float4* o4 = (float4*)(out + (size_t)b * N_OSC);
    #pragma unroll
    for (int j4 = 0; j4 < 15; ++j4) {
        float4 v;
        v.x = sTh[(4*j4 + 0)*BDIM + tid];
        v.y = sTh[(4*j4 + 1)*BDIM + tid];
        v.z = sTh[(4*j4 + 2)*BDIM + tid];
        v.w = sTh[(4*j4 + 3)*BDIM + tid];
        o4[j4] = v;
        float s, c;
        sincosf(v.x, &s, &c); ssum += s; csum += c;
        sincosf(v.y, &s, &c); ssum += s; csum += c;
        sincosf(v.z, &s, &c); ssum += s; csum += c;
        sincosf(v.w, &s, &c); ssum += s; csum += c;
    }
    ssum = __fmul_rn(ssum, 1.0f / (float)N_OSC);
    csum = __fmul_rn(csum, 1.0f / (float)N_OSC);
    out[(size_t)B * N_OSC + b] = sqrtf(__fadd_rn(__fmul_rn(csum, csum),
                                                 __fmul_rn(ssum, ssum)));
}

extern "C" void kernel_launch(void* const* d_in, const int* in_sizes, int n_in,
                              void* d_out, int out_size)
{
    const float* theta = (const float*)d_in[0];
    const float* K     = (const float*)d_in[1];
    const float* omega = (const float*)d_in[2];
    const float* p_Kg   = (const float*)d_in[3];
    const float* p_cm   = (const float*)d_in[4];
    const float* p_gate = (const float*)d_in[5];
    const float* p_csf  = (const float*)d_in[6];
    const float* p_ds   = (const float*)d_in[7];
    const float* p_rt   = (const float*)d_in[8];
    float* out = (float*)d_out;

    const int B = in_sizes[0] / N_OSC;
    const int grid = B / BDIM;

    cudaFuncSetAttribute(kuramoto_kernel,
                         cudaFuncAttributeMaxDynamicSharedMemorySize, SMEM_BYTES);

    kuramoto_kernel<<<grid, BDIM, SMEM_BYTES>>>(
        theta, K, omega, p_Kg, p_cm, p_gate, p_csf, p_ds, p_rt, out, B);
}